// round 13
// baseline (speedup 1.0000x reference)
#include <cuda_runtime.h>
#include <cstdint>

#define BB 128
#define TT 784
#define HH 256
#define LL 20
#define CC 10

#define NQUAD  32                     // 4 samples per scan task
#define CHUNK  112
#define NCHUNK 7                      // 7*112 = 784
#define NTASK  (LL * 2 * NQUAD)       // 1280
#define NCTA   147
#define NTHR   512

// Scratch (device globals: allocation-free per harness rules)
__device__ float g_xp[(size_t)BB * TT * HH];
__device__ float g_h [(size_t)BB * TT * HH];
__device__ int   g_hprog[LL * NQUAD];          // scan progress (t steps done)
__device__ int   g_xprog[LL * NQUAD];          // xp rows available for layer l
__device__ int   g_task;                        // dynamic task counter

// scan smem: h buffers [2 buf][4 samples][272 fl] = 8704B, then per-thread W
// (16 f4 data + 1 f4 pad = 68 fl stride -> 4-wf private reads, the floor).
// proj smem overlay: Ash 128x17 @0 (8704B), Bsh 16x132 @8704 (8448B).
#define SAMP_STRIDE 272               // 4 chunks x 68 (64 + 4 pad)
#define BUF_STRIDE  (4 * SAMP_STRIDE) // 1088
#define SM_W_OFF    8704
#define SM_W_STRIDE 68
#define SMEM_DYN    (SM_W_OFF + NTHR * SM_W_STRIDE * 4)   // 147968

// ---------------------------------------------------------------------------
__device__ __forceinline__ void ffma2(float2& c, float2 a, float2 b) {
    union U { float2 f; unsigned long long u; };
    U A, Bv, C;
    A.f = a; Bv.f = b; C.f = c;
    asm("fma.rn.f32x2 %0, %1, %2, %3;"
        : "=l"(C.u) : "l"(A.u), "l"(Bv.u), "l"(C.u));
    c = C.f;
}

// ---------------------------------------------------------------------------
// Layer-0 projection + watermark/counter reset: xp = x*W0 + b0 (I==1)
// ---------------------------------------------------------------------------
__global__ void proj0_kernel(const float* __restrict__ x,
                             const float* __restrict__ W0,
                             const float* __restrict__ b0) {
    int row = blockIdx.x;
    int j   = threadIdx.x;
    if (j == 0 && row < LL * NQUAD) {           // replay-safe reset
        g_hprog[row] = 0;
        g_xprog[row] = (row < NQUAD) ? TT : 0;  // layer-0 xp filled here
        if (row == 0) g_task = 0;
    }
    g_xp[(size_t)row * HH + j] = x[row] * W0[j] + b0[j];
}

// ---------------------------------------------------------------------------
// Persistent wavefront kernel. 147 CTAs x 512 threads, dynamic task grab.
// Task q: l = q>>6, r = q&63, c = r>>1 (quad id), r&1 -> proj.
// Deps point to strictly smaller q; counter grab is monotone -> no deadlock.
// ---------------------------------------------------------------------------
__global__ __launch_bounds__(NTHR, 1)
void wave_kernel(const float* __restrict__ Whh,
                 const float* __restrict__ bhh,
                 const float* __restrict__ Wih,
                 const float* __restrict__ bih) {
    extern __shared__ __align__(16) char smem_raw[];
    __shared__ int s_q;
    const int tid = threadIdx.x;

    for (;;) {
        if (tid == 0) s_q = atomicAdd(&g_task, 1);
        __syncthreads();
        const int q = s_q;
        __syncthreads();               // everyone read s_q before next overwrite
        if (q >= NTASK) break;

        const int l = q >> 6;
        const int r = q & 63;
        const int c = r >> 1;          // quad id 0..31

        if ((r & 1) == 0) {
            // ===================== SCAN(l, c): samples 4c..4c+3 =====================
            // Thread (j2 = tid>>2, kq = tid&3): cols c0 = 2*j2, c0+1;
            // k in [kq*64, +64). W row c0 in regs (16 f4), row c0+1 in
            // private smem (16 f4). Per warp/step: h 64 wf + W 64 wf = 128;
            // FMA 256 ffma2. Both pipes at the 2048 cyc/SM floor, 4 warps/SMSP.
            float* sm_h = (float*)smem_raw;
            float* myw  = (float*)(smem_raw + SM_W_OFF) + tid * SM_W_STRIDE;

            const int j2 = tid >> 2;            // 0..127
            const int kq = tid & 3;
            const int c0 = 2 * j2;
            const int k0 = kq * 64;

            const float* W0r = Whh + ((size_t)l * HH + c0) * HH + k0;
            const float* W1r = W0r + HH;

            float4 wr[16];
#pragma unroll
            for (int i = 0; i < 16; i++) wr[i] = *(const float4*)(W0r + 4 * i);
#pragma unroll
            for (int i = 0; i < 16; i++)
                *(float4*)(myw + 4 * i) = *(const float4*)(W1r + 4 * i);

            float2 bj = make_float2(0.f, 0.f);
            if (kq == 0) bj = *(const float2*)(bhh + l * HH + c0);

            for (int i = tid; i < 2 * BUF_STRIDE; i += NTHR) sm_h[i] = 0.0f;
            __syncthreads();

            const float* xp[4];
            float*       ho[4];
#pragma unroll
            for (int s = 0; s < 4; s++) {
                xp[s] = g_xp + (size_t)(4 * c + s) * TT * HH + c0;
                ho[s] = g_h  + (size_t)(4 * c + s) * TT * HH + c0;
            }

            const int rdo   = kq * 68;                      // read base in sample
            const int wslot = (c0 >> 6) * 68 + (c0 & 63);   // write offset

            int cur = 0;
            for (int ch = 0; ch < NCHUNK; ch++) {
                if (tid == 0) {
                    const int need = (ch + 1) * CHUNK;
                    while (((volatile int*)g_xprog)[l * NQUAD + c] < need)
                        __nanosleep(200);
                }
                __syncthreads();
                __threadfence();   // acquire: order xp reads after flag

#pragma unroll 1
                for (int tt = 0; tt < CHUNK; tt++) {
                    float2 xv[4];
                    if (kq == 0) {
#pragma unroll
                        for (int s = 0; s < 4; s++) xv[s] = *(const float2*)xp[s];
                    }
#pragma unroll
                    for (int s = 0; s < 4; s++) xp[s] += HH;

                    const float* hb = sm_h + cur * BUF_STRIDE + rdo;

                    float2 acc[2][4];   // [row][sample]
#pragma unroll
                    for (int rr = 0; rr < 2; rr++)
#pragma unroll
                        for (int s = 0; s < 4; s++)
                            acc[rr][s] = make_float2(0.f, 0.f);

#pragma unroll
                    for (int i = 0; i < 16; i++) {
                        float4 w0 = wr[i];
                        float4 w1 = *(const float4*)(myw + 4 * i);
#pragma unroll
                        for (int s = 0; s < 4; s++) {
                            float4 h = *(const float4*)(hb + s * SAMP_STRIDE + 4 * i);
                            ffma2(acc[0][s], make_float2(w0.x, w0.y), make_float2(h.x, h.y));
                            ffma2(acc[0][s], make_float2(w0.z, w0.w), make_float2(h.z, h.w));
                            ffma2(acc[1][s], make_float2(w1.x, w1.y), make_float2(h.x, h.y));
                            ffma2(acc[1][s], make_float2(w1.z, w1.w), make_float2(h.z, h.w));
                        }
                    }

                    float v[2][4];
#pragma unroll
                    for (int rr = 0; rr < 2; rr++)
#pragma unroll
                        for (int s = 0; s < 4; s++) {
                            float t2 = acc[rr][s].x + acc[rr][s].y;
                            // combine the 4 kq partials (lanes kq=0..3 adjacent)
                            t2 += __shfl_down_sync(0xffffffffu, t2, 1, 4);
                            t2 += __shfl_down_sync(0xffffffffu, t2, 2, 4);
                            v[rr][s] = t2;
                        }

                    int nxt = cur ^ 1;
                    if (kq == 0) {
#pragma unroll
                        for (int s = 0; s < 4; s++) {
                            float2 o;
                            o.x = fmaxf(xv[s].x + bj.x + v[0][s], 0.f);
                            o.y = fmaxf(xv[s].y + bj.y + v[1][s], 0.f);
                            *(float2*)(sm_h + nxt * BUF_STRIDE + s * SAMP_STRIDE + wslot) = o;
                            *(float2*)ho[s] = o;
                        }
                    }
#pragma unroll
                    for (int s = 0; s < 4; s++) ho[s] += HH;
                    __syncthreads();   // h(t) ready for step t+1
                    cur = nxt;
                }

                __threadfence();       // each thread fences its own h STGs
                __syncthreads();
                if (tid == 0)
                    ((volatile int*)g_hprog)[l * NQUAD + c] = (ch + 1) * CHUNK;
            }
        } else if (l < LL - 1) {
            // ===================== PROJ(l, c): h^l -> xp^{l+1} =====================
            // R11 structure at 512 threads: 8 subtiles (4 samples x 2 col-tiles),
            // tx = tid&15 (8 cols), ty = tid>>4 (4 rows each of 128; guard <112).
            float (*Ash)[17]  = (float(*)[17])smem_raw;
            float (*Bsh)[132] = (float(*)[132])(smem_raw + 8704);

            const float* Bw   = Wih + (size_t)l * HH * HH;
            const float* bias = bih + (size_t)l * HH;

            const int tx = tid & 15;      // 8 cols each
            const int ty = tid >> 4;      // 4 rows each

            for (int ch = 0; ch < NCHUNK; ch++) {
                if (tid == 0) {
                    const int need = (ch + 1) * CHUNK;
                    while (((volatile int*)g_hprog)[l * NQUAD + c] < need)
                        __nanosleep(200);
                }
                __syncthreads();
                __threadfence();   // acquire: order h reads after flag

#pragma unroll 1
                for (int sub = 0; sub < 8; sub++) {
                    const int s  = sub >> 1;                      // sample 0..3
                    const int cb = (sub & 1) * 128;               // col tile
                    const size_t rowbase = (size_t)(4 * c + s) * TT + ch * CHUNK;

                    float2 acc[4][4];
#pragma unroll
                    for (int i = 0; i < 4; i++)
#pragma unroll
                        for (int jp = 0; jp < 4; jp++) acc[i][jp] = make_float2(0.f, 0.f);

                    for (int kt = 0; kt < HH; kt += 16) {
#pragma unroll
                        for (int p = 0; p < 4; p++) {
                            int f = tid + p * NTHR;
                            int m = f >> 4, k = f & 15;
                            Ash[m][k] = (m < CHUNK)
                                ? g_h[(rowbase + m) * HH + kt + k] : 0.0f;
                        }
#pragma unroll
                        for (int p = 0; p < 4; p++) {
                            int f = tid + p * NTHR;
                            int n = f >> 4, k = f & 15;
                            Bsh[k][n] = Bw[(size_t)(cb + n) * HH + kt + k];
                        }
                        __syncthreads();
#pragma unroll
                        for (int kk = 0; kk < 16; kk++) {
                            float4 bv0 = *(const float4*)&Bsh[kk][tx * 8];
                            float4 bv1 = *(const float4*)&Bsh[kk][tx * 8 + 4];
                            float2 bp[4] = { {bv0.x, bv0.y}, {bv0.z, bv0.w},
                                             {bv1.x, bv1.y}, {bv1.z, bv1.w} };
#pragma unroll
                            for (int i = 0; i < 4; i++) {
                                float av = Ash[ty * 4 + i][kk];
                                float2 aa = {av, av};
#pragma unroll
                                for (int jp = 0; jp < 4; jp++)
                                    ffma2(acc[i][jp], aa, bp[jp]);
                            }
                        }
                        __syncthreads();
                    }

                    float bjv[8];
#pragma unroll
                    for (int jj = 0; jj < 8; jj++) bjv[jj] = bias[cb + tx * 8 + jj];
#pragma unroll
                    for (int i = 0; i < 4; i++) {
                        int m = ty * 4 + i;
                        if (m < CHUNK) {
#pragma unroll
                            for (int jp = 0; jp < 4; jp++) {
                                g_xp[(rowbase + m) * HH + cb + tx * 8 + 2 * jp]     = acc[i][jp].x + bjv[2 * jp];
                                g_xp[(rowbase + m) * HH + cb + tx * 8 + 2 * jp + 1] = acc[i][jp].y + bjv[2 * jp + 1];
                            }
                        }
                    }
                }

                // publish xp progress for layer l+1 (also releases the g_h
                // WAR hazard for scan(l+1,c))
                __threadfence();
                __syncthreads();
                if (tid == 0)
                    ((volatile int*)g_xprog)[(l + 1) * NQUAD + c] = (ch + 1) * CHUNK;
            }
        }
        __syncthreads();   // smem reuse barrier between tasks
    }
}

// ---------------------------------------------------------------------------
// Final FC: out[b,c] = sum_k h[b,T-1,k]*W_fc[c,k] + b_fc[c]
// ---------------------------------------------------------------------------
__global__ void fc_kernel(const float* __restrict__ Wfc,
                          const float* __restrict__ bfc,
                          float* __restrict__ out) {
    int b   = blockIdx.x;
    int tid = threadIdx.x;
    __shared__ float red[8];
    float hv = g_h[((size_t)b * TT + (TT - 1)) * HH + tid];
#pragma unroll
    for (int c = 0; c < CC; c++) {
        float p = hv * Wfc[(size_t)c * HH + tid];
#pragma unroll
        for (int o = 16; o > 0; o >>= 1)
            p += __shfl_down_sync(0xffffffffu, p, o);
        if ((tid & 31) == 0) red[tid >> 5] = p;
        __syncthreads();
        if (tid == 0) {
            float s = 0.0f;
#pragma unroll
            for (int w = 0; w < 8; w++) s += red[w];
            out[b * CC + c] = s + bfc[c];
        }
        __syncthreads();
    }
}

// ---------------------------------------------------------------------------
extern "C" void kernel_launch(void* const* d_in, const int* in_sizes, int n_in,
                              void* d_out, int out_size) {
    const float* x      = (const float*)d_in[0];
    const float* W_ih0  = (const float*)d_in[1];
    const float* b_ih0  = (const float*)d_in[2];
    const float* W_ih   = (const float*)d_in[3];
    const float* b_ih   = (const float*)d_in[4];
    const float* W_hh   = (const float*)d_in[5];
    const float* b_hh   = (const float*)d_in[6];
    const float* W_fc   = (const float*)d_in[7];
    const float* b_fc   = (const float*)d_in[8];
    float*       out    = (float*)d_out;

    static int smem_set = 0;
    if (!smem_set) {
        cudaFuncSetAttribute(wave_kernel,
                             cudaFuncAttributeMaxDynamicSharedMemorySize, SMEM_DYN);
        smem_set = 1;
    }

    proj0_kernel<<<BB * TT, HH>>>(x, W_ih0, b_ih0);
    wave_kernel<<<NCTA, NTHR, SMEM_DYN>>>(W_hh, b_hh, W_ih, b_ih);
    fc_kernel<<<BB, HH>>>(W_fc, b_fc, out);
}

// round 14
// speedup vs baseline: 1.0797x; 1.0797x over previous
#include <cuda_runtime.h>
#include <cstdint>

#define BB 128
#define TT 784
#define HH 256
#define LL 20
#define CC 10

#define NQUAD  16                     // 8 samples per scan task
#define CHUNK  112
#define NCHUNK 7                      // 7*112 = 784
#define NTASK  (LL * 2 * NQUAD)       // 640
#define NCTA   147
#define NTHR   256

// Scratch (device globals: allocation-free per harness rules)
__device__ float g_xp[(size_t)BB * TT * HH];
__device__ float g_h [(size_t)BB * TT * HH];
__device__ int   g_hprog[LL * NQUAD];          // scan progress (t steps done)
__device__ int   g_xprog[LL * NQUAD];          // xp rows available for layer l
__device__ int   g_task;                        // dynamic task counter

// scan smem: h buffers [2 buf][8 samples][260 fl] = 16640B, then per-thread W
// (48 f4 data + 1 f4 pad = 196 fl stride; 196 % 32 == 4 -> conflict-free
// 4-wf LDS.128 reads). proj overlay: Ash 128x17 @0, Bsh 16x132 @8704.
#define SAMP_STRIDE 260               // 256 + 4 pad between kh halves
#define BUF_STRIDE  (8 * SAMP_STRIDE) // 2080
#define SM_W_OFF    16640
#define SM_W_STRIDE 196
#define SMEM_DYN    (SM_W_OFF + NTHR * SM_W_STRIDE * 4)   // 217344

#define SAMP_GL     ((size_t)TT * HH) // per-sample float stride in g_xp / g_h

// ---------------------------------------------------------------------------
__device__ __forceinline__ void ffma2(float2& c, float2 a, float2 b) {
    union U { float2 f; unsigned long long u; };
    U A, Bv, C;
    A.f = a; Bv.f = b; C.f = c;
    asm("fma.rn.f32x2 %0, %1, %2, %3;"
        : "=l"(C.u) : "l"(A.u), "l"(Bv.u), "l"(C.u));
    c = C.f;
}

// ---------------------------------------------------------------------------
// Layer-0 projection + watermark/counter reset: xp = x*W0 + b0 (I==1)
// ---------------------------------------------------------------------------
__global__ void proj0_kernel(const float* __restrict__ x,
                             const float* __restrict__ W0,
                             const float* __restrict__ b0) {
    int row = blockIdx.x;
    int j   = threadIdx.x;
    if (j == 0 && row < LL * NQUAD) {           // replay-safe reset
        g_hprog[row] = 0;
        g_xprog[row] = (row < NQUAD) ? TT : 0;  // layer-0 xp filled here
        if (row == 0) g_task = 0;
    }
    g_xp[(size_t)row * HH + j] = x[row] * W0[j] + b0[j];
}

// ---------------------------------------------------------------------------
// Persistent wavefront kernel. 147 CTAs x 256 threads, dynamic task grab.
// Task q: l = q>>5, r = q&31, c = r>>1 (octet id), r&1 -> proj.
// Deps point to strictly smaller q; counter grab is monotone -> no deadlock.
// ---------------------------------------------------------------------------
__global__ __launch_bounds__(NTHR, 1)
void wave_kernel(const float* __restrict__ Whh,
                 const float* __restrict__ bhh,
                 const float* __restrict__ Wih,
                 const float* __restrict__ bih) {
    extern __shared__ __align__(16) char smem_raw[];
    __shared__ int s_q;
    const int tid = threadIdx.x;

    for (;;) {
        if (tid == 0) s_q = atomicAdd(&g_task, 1);
        __syncthreads();
        const int q = s_q;
        __syncthreads();               // everyone read s_q before next overwrite
        if (q >= NTASK) break;

        const int l = q >> 5;
        const int r = q & 31;
        const int c = r >> 1;          // octet id 0..15

        if ((r & 1) == 0) {
            // ============== SCAN(l, c): samples 8c..8c+7 ==============
            // Thread (j2 = tid>>1, kh = tid&1): cols c0 = 2*j2, c0+1;
            // k in [kh*128, +128). W: 16 f4 regs + 48 f4 private smem.
            // Per step/SM: FMA 4096 cyc, crossbar (256 h + 192 W) wf = 3584
            // -> FMA-bound; per-step fixed overhead amortized over 8 samples.
            float* sm_h = (float*)smem_raw;
            float* myw  = (float*)(smem_raw + SM_W_OFF) + tid * SM_W_STRIDE;

            const int j2 = tid >> 1;
            const int kh = tid & 1;
            const int c0 = 2 * j2;
            const int k0 = kh * 128;

            const float* W0r = Whh + ((size_t)l * HH + c0) * HH + k0;
            const float* W1r = W0r + HH;

            // regs: row c0 k-chunk [0,64)
            float4 wr[16];
#pragma unroll
            for (int i = 0; i < 16; i++) wr[i] = *(const float4*)(W0r + 4 * i);
            // smem: [0..15] row c0+1 chunk [0,64); [16..31] row c0 [64,128);
            //       [32..47] row c0+1 [64,128)
#pragma unroll
            for (int i = 0; i < 16; i++) {
                *(float4*)(myw + 4 * i)        = *(const float4*)(W1r + 4 * i);
                *(float4*)(myw + 64 + 4 * i)   = *(const float4*)(W0r + 64 + 4 * i);
                *(float4*)(myw + 128 + 4 * i)  = *(const float4*)(W1r + 64 + 4 * i);
            }

            float2 bj = make_float2(0.f, 0.f);
            if (kh == 0) bj = *(const float2*)(bhh + l * HH + c0);

            for (int i = tid; i < 2 * BUF_STRIDE; i += NTHR) sm_h[i] = 0.0f;
            __syncthreads();

            const float* xpb = g_xp + (size_t)(8 * c) * SAMP_GL + c0;
            float*       hob = g_h  + (size_t)(8 * c) * SAMP_GL + c0;

            const int rdo   = kh * 132;                 // read base in sample
            const int wslot = c0 + (c0 >= 128 ? 4 : 0); // write offset

            int cur = 0;
            size_t roff = 0;                            // t * HH
            for (int ch = 0; ch < NCHUNK; ch++) {
                if (tid == 0) {
                    const int need = (ch + 1) * CHUNK;
                    while (((volatile int*)g_xprog)[l * NQUAD + c] < need)
                        __nanosleep(200);
                }
                __syncthreads();
                __threadfence();   // acquire: order xp reads after flag

#pragma unroll 1
                for (int tt = 0; tt < CHUNK; tt++) {
                    float2 xv[8];
                    if (kh == 0) {
#pragma unroll
                        for (int s = 0; s < 8; s++)
                            xv[s] = *(const float2*)(xpb + s * SAMP_GL + roff);
                    }

                    const float* hb = sm_h + cur * BUF_STRIDE + rdo;

                    float2 aA[2][8], aB[2][8];   // [row][sample]
#pragma unroll
                    for (int rr = 0; rr < 2; rr++)
#pragma unroll
                        for (int s = 0; s < 8; s++) {
                            aA[rr][s] = make_float2(0.f, 0.f);
                            aB[rr][s] = make_float2(0.f, 0.f);
                        }

#pragma unroll
                    for (int i = 0; i < 32; i++) {
                        float4 w0 = (i < 16) ? wr[i]
                                             : *(const float4*)(myw + 64 + 4 * (i - 16));
                        float4 w1 = (i < 16) ? *(const float4*)(myw + 4 * i)
                                             : *(const float4*)(myw + 128 + 4 * (i - 16));
#pragma unroll
                        for (int s = 0; s < 8; s++) {
                            float4 h = *(const float4*)(hb + s * SAMP_STRIDE + 4 * i);
                            ffma2(aA[0][s], make_float2(w0.x, w0.y), make_float2(h.x, h.y));
                            ffma2(aB[0][s], make_float2(w0.z, w0.w), make_float2(h.z, h.w));
                            ffma2(aA[1][s], make_float2(w1.x, w1.y), make_float2(h.x, h.y));
                            ffma2(aB[1][s], make_float2(w1.z, w1.w), make_float2(h.z, h.w));
                        }
                    }

                    int nxt = cur ^ 1;
#pragma unroll
                    for (int s = 0; s < 8; s++) {
                        float v0 = (aA[0][s].x + aA[0][s].y) + (aB[0][s].x + aB[0][s].y);
                        float v1 = (aA[1][s].x + aA[1][s].y) + (aB[1][s].x + aB[1][s].y);
                        // combine kh=0 / kh=1 partials (adjacent lanes)
                        v0 += __shfl_down_sync(0xffffffffu, v0, 1, 2);
                        v1 += __shfl_down_sync(0xffffffffu, v1, 1, 2);
                        if (kh == 0) {
                            float2 o;
                            o.x = fmaxf(xv[s].x + bj.x + v0, 0.f);
                            o.y = fmaxf(xv[s].y + bj.y + v1, 0.f);
                            *(float2*)(sm_h + nxt * BUF_STRIDE + s * SAMP_STRIDE + wslot) = o;
                            *(float2*)(hob + s * SAMP_GL + roff) = o;
                        }
                    }
                    roff += HH;
                    __syncthreads();   // h(t) ready for step t+1
                    cur = nxt;
                }

                __threadfence();       // each thread fences its own h STGs
                __syncthreads();
                if (tid == 0)
                    ((volatile int*)g_hprog)[l * NQUAD + c] = (ch + 1) * CHUNK;
            }
        } else if (l < LL - 1) {
            // ============== PROJ(l, c): h^l -> xp^{l+1} ==============
            // 16 subtiles per chunk: 8 samples x 2 col-tiles, 112x128 each.
            float (*Ash)[17]  = (float(*)[17])smem_raw;
            float (*Bsh)[132] = (float(*)[132])(smem_raw + 8704);

            const float* Bw   = Wih + (size_t)l * HH * HH;
            const float* bias = bih + (size_t)l * HH;

            const int tx = tid & 15;      // 8 cols each
            const int ty = tid >> 4;      // 8 rows each

            for (int ch = 0; ch < NCHUNK; ch++) {
                if (tid == 0) {
                    const int need = (ch + 1) * CHUNK;
                    while (((volatile int*)g_hprog)[l * NQUAD + c] < need)
                        __nanosleep(200);
                }
                __syncthreads();
                __threadfence();   // acquire: order h reads after flag

#pragma unroll 1
                for (int sub = 0; sub < 16; sub++) {
                    const int s  = sub >> 1;                      // sample 0..7
                    const int cb = (sub & 1) * 128;               // col tile
                    const size_t rowbase = (size_t)(8 * c + s) * TT + ch * CHUNK;

                    float2 acc[8][4];
#pragma unroll
                    for (int i = 0; i < 8; i++)
#pragma unroll
                        for (int jp = 0; jp < 4; jp++) acc[i][jp] = make_float2(0.f, 0.f);

                    for (int kt = 0; kt < HH; kt += 16) {
#pragma unroll
                        for (int p = 0; p < 8; p++) {
                            int f = tid + p * NTHR;
                            int m = f >> 4, k = f & 15;
                            Ash[m][k] = (m < CHUNK)
                                ? g_h[(rowbase + m) * HH + kt + k] : 0.0f;
                        }
#pragma unroll
                        for (int p = 0; p < 8; p++) {
                            int f = tid + p * NTHR;
                            int n = f >> 4, k = f & 15;
                            Bsh[k][n] = Bw[(size_t)(cb + n) * HH + kt + k];
                        }
                        __syncthreads();
#pragma unroll
                        for (int kk = 0; kk < 16; kk++) {
                            float4 bv0 = *(const float4*)&Bsh[kk][tx * 8];
                            float4 bv1 = *(const float4*)&Bsh[kk][tx * 8 + 4];
                            float2 bp[4] = { {bv0.x, bv0.y}, {bv0.z, bv0.w},
                                             {bv1.x, bv1.y}, {bv1.z, bv1.w} };
#pragma unroll
                            for (int i = 0; i < 8; i++) {
                                float av = Ash[ty * 8 + i][kk];
                                float2 aa = {av, av};
#pragma unroll
                                for (int jp = 0; jp < 4; jp++)
                                    ffma2(acc[i][jp], aa, bp[jp]);
                            }
                        }
                        __syncthreads();
                    }

                    float bjv[8];
#pragma unroll
                    for (int jj = 0; jj < 8; jj++) bjv[jj] = bias[cb + tx * 8 + jj];
#pragma unroll
                    for (int i = 0; i < 8; i++) {
                        int m = ty * 8 + i;
                        if (m < CHUNK) {
#pragma unroll
                            for (int jp = 0; jp < 4; jp++) {
                                g_xp[(rowbase + m) * HH + cb + tx * 8 + 2 * jp]     = acc[i][jp].x + bjv[2 * jp];
                                g_xp[(rowbase + m) * HH + cb + tx * 8 + 2 * jp + 1] = acc[i][jp].y + bjv[2 * jp + 1];
                            }
                        }
                    }
                }

                // publish xp progress for layer l+1 (also releases the g_h
                // WAR hazard for scan(l+1,c))
                __threadfence();
                __syncthreads();
                if (tid == 0)
                    ((volatile int*)g_xprog)[(l + 1) * NQUAD + c] = (ch + 1) * CHUNK;
            }
        }
        __syncthreads();   // smem reuse barrier between tasks
    }
}

// ---------------------------------------------------------------------------
// Final FC: out[b,c] = sum_k h[b,T-1,k]*W_fc[c,k] + b_fc[c]
// ---------------------------------------------------------------------------
__global__ void fc_kernel(const float* __restrict__ Wfc,
                          const float* __restrict__ bfc,
                          float* __restrict__ out) {
    int b   = blockIdx.x;
    int tid = threadIdx.x;
    __shared__ float red[8];
    float hv = g_h[((size_t)b * TT + (TT - 1)) * HH + tid];
#pragma unroll
    for (int c = 0; c < CC; c++) {
        float p = hv * Wfc[(size_t)c * HH + tid];
#pragma unroll
        for (int o = 16; o > 0; o >>= 1)
            p += __shfl_down_sync(0xffffffffu, p, o);
        if ((tid & 31) == 0) red[tid >> 5] = p;
        __syncthreads();
        if (tid == 0) {
            float s = 0.0f;
#pragma unroll
            for (int w = 0; w < 8; w++) s += red[w];
            out[b * CC + c] = s + bfc[c];
        }
        __syncthreads();
    }
}

// ---------------------------------------------------------------------------
extern "C" void kernel_launch(void* const* d_in, const int* in_sizes, int n_in,
                              void* d_out, int out_size) {
    const float* x      = (const float*)d_in[0];
    const float* W_ih0  = (const float*)d_in[1];
    const float* b_ih0  = (const float*)d_in[2];
    const float* W_ih   = (const float*)d_in[3];
    const float* b_ih   = (const float*)d_in[4];
    const float* W_hh   = (const float*)d_in[5];
    const float* b_hh   = (const float*)d_in[6];
    const float* W_fc   = (const float*)d_in[7];
    const float* b_fc   = (const float*)d_in[8];
    float*       out    = (float*)d_out;

    static int smem_set = 0;
    if (!smem_set) {
        cudaFuncSetAttribute(wave_kernel,
                             cudaFuncAttributeMaxDynamicSharedMemorySize, SMEM_DYN);
        smem_set = 1;
    }

    proj0_kernel<<<BB * TT, HH>>>(x, W_ih0, b_ih0);
    wave_kernel<<<NCTA, NTHR, SMEM_DYN>>>(W_hh, b_hh, W_ih, b_ih);
    fc_kernel<<<BB, HH>>>(W_fc, b_fc, out);
}

// round 15
// speedup vs baseline: 1.2004x; 1.1118x over previous
#include <cuda_runtime.h>
#include <cstdint>

#define BB 128
#define TT 784
#define HH 256
#define LL 20
#define CC 10

#define NQUAD  32                     // 4 samples per scan task
#define CHUNK  112
#define NCHUNK 7                      // 7*112 = 784
#define NTASK  (LL * 2 * NQUAD)       // 1280
#define NCTA   147

// Scratch (device globals: allocation-free per harness rules)
__device__ float g_xp[(size_t)BB * TT * HH];
__device__ float g_h [(size_t)BB * TT * HH];
__device__ int   g_hprog[LL * NQUAD];          // scan progress (t steps done)
__device__ int   g_xprog[LL * NQUAD];          // xp rows available for layer l
__device__ int   g_task;                        // dynamic task counter

// scan smem: h buffers [2 buf][4 samples][260 fl] = 8320B, then per-thread W
// (16 f4 data + 1 f4 pad = 68 fl stride -> 4-wf private reads, the floor).
// proj smem overlay: Ash 128x17 @0, Bsh 16x132 @8704.
#define SAMP_STRIDE 260               // 256 + 4 pad between kh halves
#define BUF_STRIDE  (4 * SAMP_STRIDE) // 1040
#define SM_W_OFF    8320
#define SM_W_STRIDE 68
#define SMEM_DYN    (SM_W_OFF + 256 * SM_W_STRIDE * 4)   // 77952

// ---------------------------------------------------------------------------
__device__ __forceinline__ void ffma2(float2& c, float2 a, float2 b) {
    union U { float2 f; unsigned long long u; };
    U A, Bv, C;
    A.f = a; Bv.f = b; C.f = c;
    asm("fma.rn.f32x2 %0, %1, %2, %3;"
        : "=l"(C.u) : "l"(A.u), "l"(Bv.u), "l"(C.u));
    c = C.f;
}

// ---------------------------------------------------------------------------
// Layer-0 projection + watermark/counter reset: xp = x*W0 + b0 (I==1)
// ---------------------------------------------------------------------------
__global__ void proj0_kernel(const float* __restrict__ x,
                             const float* __restrict__ W0,
                             const float* __restrict__ b0) {
    int row = blockIdx.x;
    int j   = threadIdx.x;
    if (j == 0 && row < LL * NQUAD) {           // replay-safe reset
        g_hprog[row] = 0;
        g_xprog[row] = (row < NQUAD) ? TT : 0;  // layer-0 xp filled here
        if (row == 0) g_task = 0;
    }
    g_xp[(size_t)row * HH + j] = x[row] * W0[j] + b0[j];
}

// ---------------------------------------------------------------------------
// Persistent wavefront kernel. 147 CTAs x 256 threads, dynamic task grab.
// Task q: l = q>>6, r = q&63, c = r>>1 (quad id), r&1 -> proj.
// Deps point to strictly smaller q; counter grab is monotone -> no deadlock.
// ---------------------------------------------------------------------------
__global__ __launch_bounds__(256, 1)
void wave_kernel(const float* __restrict__ Whh,
                 const float* __restrict__ bhh,
                 const float* __restrict__ Wih,
                 const float* __restrict__ bih) {
    extern __shared__ __align__(16) char smem_raw[];
    __shared__ int s_q;
    const int tid = threadIdx.x;

    for (;;) {
        if (tid == 0) s_q = atomicAdd(&g_task, 1);
        __syncthreads();
        const int q = s_q;
        __syncthreads();               // everyone read s_q before next overwrite
        if (q >= NTASK) break;

        const int l = q >> 6;
        const int r = q & 63;
        const int c = r >> 1;          // quad id 0..31

        if ((r & 1) == 0) {
            // ===================== SCAN(l, c): samples 4c..4c+3 =====================
            // Thread (j2 = tid>>1, kh = tid&1): cols c0 = 2*j2, c0+1;
            // k in [kh*128, +128). W row c0 fully in regs (32 f4), row c0+1
            // split 16 f4 regs + 16 f4 private smem (crossbar 192 wf/warp vs
            // FMA 2048 cyc/SM -> FMA-bound with headroom).
            float* sm_h = (float*)smem_raw;
            float* myw  = (float*)(smem_raw + SM_W_OFF) + tid * SM_W_STRIDE;

            const int j2 = tid >> 1;
            const int kh = tid & 1;
            const int c0 = 2 * j2;
            const int k0 = kh * 128;

            const float* W0r = Whh + ((size_t)l * HH + c0) * HH + k0;
            const float* W1r = W0r + HH;

            float4 wr[48];
#pragma unroll
            for (int i = 0; i < 32; i++) wr[i] = *(const float4*)(W0r + 4 * i);
#pragma unroll
            for (int i = 0; i < 16; i++) wr[32 + i] = *(const float4*)(W1r + 4 * i);
#pragma unroll
            for (int i = 0; i < 16; i++)
                *(float4*)(myw + 4 * i) = *(const float4*)(W1r + 64 + 4 * i);

            float2 bj = make_float2(0.f, 0.f);
            if (kh == 0) bj = *(const float2*)(bhh + l * HH + c0);

            for (int i = tid; i < 2 * BUF_STRIDE; i += 256) sm_h[i] = 0.0f;
            __syncthreads();

            const float* xp[4];
            float*       ho[4];
#pragma unroll
            for (int s = 0; s < 4; s++) {
                xp[s] = g_xp + (size_t)(4 * c + s) * TT * HH + c0;
                ho[s] = g_h  + (size_t)(4 * c + s) * TT * HH + c0;
            }

            const int rdo   = kh * 132;                 // read base within sample
            const int wslot = c0 + (c0 >= 128 ? 4 : 0); // write offset

            int cur = 0;
            for (int ch = 0; ch < NCHUNK; ch++) {
                if (tid == 0) {
                    const int need = (ch + 1) * CHUNK;
                    while (((volatile int*)g_xprog)[l * NQUAD + c] < need)
                        __nanosleep(200);
                }
                __syncthreads();
                __threadfence();   // acquire: order xp reads after flag

#pragma unroll 1
                for (int tt = 0; tt < CHUNK; tt++) {
                    float2 xv[4];
                    if (kh == 0) {
#pragma unroll
                        for (int s = 0; s < 4; s++) xv[s] = *(const float2*)xp[s];
                    }
#pragma unroll
                    for (int s = 0; s < 4; s++) xp[s] += HH;

                    const float* hb = sm_h + cur * BUF_STRIDE + rdo;

                    float2 aA[2][4], aB[2][4];   // [row][sample]
#pragma unroll
                    for (int rr = 0; rr < 2; rr++)
#pragma unroll
                        for (int s = 0; s < 4; s++) {
                            aA[rr][s] = make_float2(0.f, 0.f);
                            aB[rr][s] = make_float2(0.f, 0.f);
                        }

#pragma unroll
                    for (int i = 0; i < 32; i++) {
                        float4 w0 = wr[i];
                        float4 w1 = (i < 16) ? wr[32 + i]
                                             : *(const float4*)(myw + 4 * (i - 16));
#pragma unroll
                        for (int s = 0; s < 4; s++) {
                            float4 h = *(const float4*)(hb + s * SAMP_STRIDE + 4 * i);
                            ffma2(aA[0][s], make_float2(w0.x, w0.y), make_float2(h.x, h.y));
                            ffma2(aB[0][s], make_float2(w0.z, w0.w), make_float2(h.z, h.w));
                            ffma2(aA[1][s], make_float2(w1.x, w1.y), make_float2(h.x, h.y));
                            ffma2(aB[1][s], make_float2(w1.z, w1.w), make_float2(h.z, h.w));
                        }
                    }

                    float v[2][4];
#pragma unroll
                    for (int rr = 0; rr < 2; rr++)
#pragma unroll
                        for (int s = 0; s < 4; s++) {
                            float t2 = (aA[rr][s].x + aA[rr][s].y)
                                     + (aB[rr][s].x + aB[rr][s].y);
                            t2 += __shfl_down_sync(0xffffffffu, t2, 1, 2);
                            v[rr][s] = t2;
                        }

                    int nxt = cur ^ 1;
                    if (kh == 0) {
#pragma unroll
                        for (int s = 0; s < 4; s++) {
                            float2 o;
                            o.x = fmaxf(xv[s].x + bj.x + v[0][s], 0.f);
                            o.y = fmaxf(xv[s].y + bj.y + v[1][s], 0.f);
                            *(float2*)(sm_h + nxt * BUF_STRIDE + s * SAMP_STRIDE + wslot) = o;
                            *(float2*)ho[s] = o;
                        }
                    }
#pragma unroll
                    for (int s = 0; s < 4; s++) ho[s] += HH;
                    __syncthreads();   // h(t) ready for step t+1
                    cur = nxt;
                }

                __threadfence();       // each thread fences its own h STGs
                __syncthreads();
                if (tid == 0)
                    ((volatile int*)g_hprog)[l * NQUAD + c] = (ch + 1) * CHUNK;
            }
        } else if (l < LL - 1) {
            // ===================== PROJ(l, c): h^l -> xp^{l+1} =====================
            float (*Ash)[17]  = (float(*)[17])smem_raw;
            float (*Bsh)[132] = (float(*)[132])(smem_raw + 8704);

            const float* Bw   = Wih + (size_t)l * HH * HH;
            const float* bias = bih + (size_t)l * HH;

            const int tx = tid & 15;      // 8 cols each
            const int ty = tid >> 4;      // 8 rows each

            for (int ch = 0; ch < NCHUNK; ch++) {
                if (tid == 0) {
                    const int need = (ch + 1) * CHUNK;
                    while (((volatile int*)g_hprog)[l * NQUAD + c] < need)
                        __nanosleep(200);
                }
                __syncthreads();
                __threadfence();   // acquire: order h reads after flag

#pragma unroll 1
                for (int sub = 0; sub < 8; sub++) {
                    const int s  = sub >> 1;                      // sample 0..3
                    const int cb = (sub & 1) * 128;               // col tile
                    const size_t rowbase = (size_t)(4 * c + s) * TT + ch * CHUNK;

                    float2 acc[8][4];
#pragma unroll
                    for (int i = 0; i < 8; i++)
#pragma unroll
                        for (int jp = 0; jp < 4; jp++) acc[i][jp] = make_float2(0.f, 0.f);

                    for (int kt = 0; kt < HH; kt += 16) {
#pragma unroll
                        for (int p = 0; p < 8; p++) {
                            int f = tid + p * 256;
                            int m = f >> 4, k = f & 15;
                            Ash[m][k] = (m < CHUNK)
                                ? g_h[(rowbase + m) * HH + kt + k] : 0.0f;
                        }
#pragma unroll
                        for (int p = 0; p < 8; p++) {
                            int f = tid + p * 256;
                            int n = f >> 4, k = f & 15;
                            Bsh[k][n] = Bw[(size_t)(cb + n) * HH + kt + k];
                        }
                        __syncthreads();
#pragma unroll
                        for (int kk = 0; kk < 16; kk++) {
                            float4 bv0 = *(const float4*)&Bsh[kk][tx * 8];
                            float4 bv1 = *(const float4*)&Bsh[kk][tx * 8 + 4];
                            float2 bp[4] = { {bv0.x, bv0.y}, {bv0.z, bv0.w},
                                             {bv1.x, bv1.y}, {bv1.z, bv1.w} };
#pragma unroll
                            for (int i = 0; i < 8; i++) {
                                float av = Ash[ty * 8 + i][kk];
                                float2 aa = {av, av};
#pragma unroll
                                for (int jp = 0; jp < 4; jp++)
                                    ffma2(acc[i][jp], aa, bp[jp]);
                            }
                        }
                        __syncthreads();
                    }

                    float bjv[8];
#pragma unroll
                    for (int jj = 0; jj < 8; jj++) bjv[jj] = bias[cb + tx * 8 + jj];
#pragma unroll
                    for (int i = 0; i < 8; i++) {
                        int m = ty * 8 + i;
                        if (m < CHUNK) {
#pragma unroll
                            for (int jp = 0; jp < 4; jp++) {
                                g_xp[(rowbase + m) * HH + cb + tx * 8 + 2 * jp]     = acc[i][jp].x + bjv[2 * jp];
                                g_xp[(rowbase + m) * HH + cb + tx * 8 + 2 * jp + 1] = acc[i][jp].y + bjv[2 * jp + 1];
                            }
                        }
                    }
                }

                // publish xp progress for layer l+1 (also releases the g_h
                // WAR hazard for scan(l+1,c))
                __threadfence();
                __syncthreads();
                if (tid == 0)
                    ((volatile int*)g_xprog)[(l + 1) * NQUAD + c] = (ch + 1) * CHUNK;
            }
        }
        __syncthreads();   // smem reuse barrier between tasks
    }
}

// ---------------------------------------------------------------------------
// Final FC: out[b,c] = sum_k h[b,T-1,k]*W_fc[c,k] + b_fc[c]
// ---------------------------------------------------------------------------
__global__ void fc_kernel(const float* __restrict__ Wfc,
                          const float* __restrict__ bfc,
                          float* __restrict__ out) {
    int b   = blockIdx.x;
    int tid = threadIdx.x;
    __shared__ float red[8];
    float hv = g_h[((size_t)b * TT + (TT - 1)) * HH + tid];
#pragma unroll
    for (int c = 0; c < CC; c++) {
        float p = hv * Wfc[(size_t)c * HH + tid];
#pragma unroll
        for (int o = 16; o > 0; o >>= 1)
            p += __shfl_down_sync(0xffffffffu, p, o);
        if ((tid & 31) == 0) red[tid >> 5] = p;
        __syncthreads();
        if (tid == 0) {
            float s = 0.0f;
#pragma unroll
            for (int w = 0; w < 8; w++) s += red[w];
            out[b * CC + c] = s + bfc[c];
        }
        __syncthreads();
    }
}

// ---------------------------------------------------------------------------
extern "C" void kernel_launch(void* const* d_in, const int* in_sizes, int n_in,
                              void* d_out, int out_size) {
    const float* x      = (const float*)d_in[0];
    const float* W_ih0  = (const float*)d_in[1];
    const float* b_ih0  = (const float*)d_in[2];
    const float* W_ih   = (const float*)d_in[3];
    const float* b_ih   = (const float*)d_in[4];
    const float* W_hh   = (const float*)d_in[5];
    const float* b_hh   = (const float*)d_in[6];
    const float* W_fc   = (const float*)d_in[7];
    const float* b_fc   = (const float*)d_in[8];
    float*       out    = (float*)d_out;

    static int smem_set = 0;
    if (!smem_set) {
        cudaFuncSetAttribute(wave_kernel,
                             cudaFuncAttributeMaxDynamicSharedMemorySize, SMEM_DYN);
        smem_set = 1;
    }

    proj0_kernel<<<BB * TT, HH>>>(x, W_ih0, b_ih0);
    wave_kernel<<<NCTA, 256, SMEM_DYN>>>(W_hh, b_hh, W_ih, b_ih);
    fc_kernel<<<BB, HH>>>(W_fc, b_fc, out);
}

// round 16
// speedup vs baseline: 1.4086x; 1.1734x over previous
#include <cuda_runtime.h>
#include <cstdint>

#define BB 128
#define TT 784
#define HH 256
#define LL 20
#define CC 10

#define NQUAD  32                     // 4 samples per scan task
#define CHUNK  112
#define NCHUNK 7                      // 7*112 = 784
#define NTASK  (LL * 2 * NQUAD)       // 1280
#define NCTA   147

// Scratch (device globals: allocation-free per harness rules)
__device__ float g_xp[(size_t)BB * TT * HH];
__device__ float g_h [(size_t)BB * TT * HH];
__device__ int   g_hprog[LL * NQUAD];          // scan progress (t steps done)
__device__ int   g_xprog[LL * NQUAD];          // xp rows available for layer l
__device__ int   g_task;                        // dynamic task counter

// scan smem: h buffers [2 buf][4 samples][260 fl] = 8320B, then per-thread W
// (32 f4 data + 1 f4 pad = 132 fl stride -> 4-wf private reads, the floor).
// proj smem: Ash 128x17 @0, Bsh 16x132 @8704 (overlaid; tasks serialized).
#define SAMP_STRIDE 260               // 256 + 4 pad between kh halves
#define BUF_STRIDE  (4 * SAMP_STRIDE) // 1040
#define SM_W_OFF    8320
#define SM_W_STRIDE 132
#define SMEM_DYN    (SM_W_OFF + 256 * SM_W_STRIDE * 4)   // 143488

// ---------------------------------------------------------------------------
__device__ __forceinline__ void ffma2(float2& c, float2 a, float2 b) {
    union U { float2 f; unsigned long long u; };
    U A, Bv, C;
    A.f = a; Bv.f = b; C.f = c;
    asm("fma.rn.f32x2 %0, %1, %2, %3;"
        : "=l"(C.u) : "l"(A.u), "l"(Bv.u), "l"(C.u));
    c = C.f;
}

// ---------------------------------------------------------------------------
// Layer-0 projection + watermark/counter reset: xp = x*W0 + b0 (I==1)
// ---------------------------------------------------------------------------
__global__ void proj0_kernel(const float* __restrict__ x,
                             const float* __restrict__ W0,
                             const float* __restrict__ b0) {
    int row = blockIdx.x;
    int j   = threadIdx.x;
    if (j == 0 && row < LL * NQUAD) {           // replay-safe reset
        g_hprog[row] = 0;
        g_xprog[row] = (row < NQUAD) ? TT : 0;  // layer-0 xp filled here
        if (row == 0) g_task = 0;
    }
    g_xp[(size_t)row * HH + j] = x[row] * W0[j] + b0[j];
}

// ---------------------------------------------------------------------------
// Persistent wavefront kernel. 147 CTAs x 256 threads, dynamic task grab.
// Task q: l = q>>6, r = q&63, c = r>>1 (quad id), r&1 -> proj.
// Deps point to strictly smaller q; counter grab is monotone -> no deadlock.
// ---------------------------------------------------------------------------
__global__ __launch_bounds__(256, 1)
void wave_kernel(const float* __restrict__ Whh,
                 const float* __restrict__ bhh,
                 const float* __restrict__ Wih,
                 const float* __restrict__ bih) {
    extern __shared__ __align__(16) char smem_raw[];
    __shared__ int s_q;
    const int tid = threadIdx.x;

    for (;;) {
        if (tid == 0) s_q = atomicAdd(&g_task, 1);
        __syncthreads();
        const int q = s_q;
        __syncthreads();               // everyone read s_q before next overwrite
        if (q >= NTASK) break;

        const int l = q >> 6;
        const int r = q & 63;
        const int c = r >> 1;          // quad id 0..31

        if ((r & 1) == 0) {
            // ===================== SCAN(l, c): samples 4c..4c+3 =====================
            // Thread (j2 = tid>>1, kh = tid&1): cols c0 = 2*j2, c0+1;
            // k in [kh*128, +128). W row c0 in regs (32 f4), row c0+1 in
            // private smem (32 f4). FMA 2048 == crossbar 2048 per step/SM
            // (the fp32 dual-issue floor; 512 cyc per sample-step).
            float* sm_h = (float*)smem_raw;
            float* myw  = (float*)(smem_raw + SM_W_OFF) + tid * SM_W_STRIDE;

            const int j2 = tid >> 1;
            const int kh = tid & 1;
            const int c0 = 2 * j2;
            const int k0 = kh * 128;

            const float* W0r = Whh + ((size_t)l * HH + c0) * HH + k0;
            const float* W1r = W0r + HH;

            float4 wr[32];
#pragma unroll
            for (int i = 0; i < 32; i++) wr[i] = *(const float4*)(W0r + 4 * i);
#pragma unroll
            for (int i = 0; i < 32; i++)
                *(float4*)(myw + 4 * i) = *(const float4*)(W1r + 4 * i);

            float2 bj = make_float2(0.f, 0.f);
            if (kh == 0) bj = *(const float2*)(bhh + l * HH + c0);

            for (int i = tid; i < 2 * BUF_STRIDE; i += 256) sm_h[i] = 0.0f;
            __syncthreads();

            const float* xp[4];
            float*       ho[4];
#pragma unroll
            for (int s = 0; s < 4; s++) {
                xp[s] = g_xp + (size_t)(4 * c + s) * TT * HH + c0;
                ho[s] = g_h  + (size_t)(4 * c + s) * TT * HH + c0;
            }

            const int rdo   = kh * 132;                 // read base within sample
            const int wslot = c0 + (c0 >= 128 ? 4 : 0); // write offset

            int cur = 0;
            for (int ch = 0; ch < NCHUNK; ch++) {
                if (tid == 0) {
                    const int need = (ch + 1) * CHUNK;
                    while (((volatile int*)g_xprog)[l * NQUAD + c] < need)
                        __nanosleep(200);
                }
                __syncthreads();
                __threadfence();   // acquire: order xp reads after flag

#pragma unroll 1
                for (int tt = 0; tt < CHUNK; tt++) {
                    float2 xv[4];
                    if (kh == 0) {
#pragma unroll
                        for (int s = 0; s < 4; s++) xv[s] = *(const float2*)xp[s];
                    }
#pragma unroll
                    for (int s = 0; s < 4; s++) xp[s] += HH;

                    const float* hb = sm_h + cur * BUF_STRIDE + rdo;

                    float2 aA[2][4], aB[2][4];   // [row][sample]
#pragma unroll
                    for (int rr = 0; rr < 2; rr++)
#pragma unroll
                        for (int s = 0; s < 4; s++) {
                            aA[rr][s] = make_float2(0.f, 0.f);
                            aB[rr][s] = make_float2(0.f, 0.f);
                        }

#pragma unroll
                    for (int i = 0; i < 32; i++) {
                        float4 w0 = wr[i];
                        float4 w1 = *(const float4*)(myw + 4 * i);
#pragma unroll
                        for (int s = 0; s < 4; s++) {
                            float4 h = *(const float4*)(hb + s * SAMP_STRIDE + 4 * i);
                            ffma2(aA[0][s], make_float2(w0.x, w0.y), make_float2(h.x, h.y));
                            ffma2(aB[0][s], make_float2(w0.z, w0.w), make_float2(h.z, h.w));
                            ffma2(aA[1][s], make_float2(w1.x, w1.y), make_float2(h.x, h.y));
                            ffma2(aB[1][s], make_float2(w1.z, w1.w), make_float2(h.z, h.w));
                        }
                    }

                    float v[2][4];
#pragma unroll
                    for (int rr = 0; rr < 2; rr++)
#pragma unroll
                        for (int s = 0; s < 4; s++) {
                            float t2 = (aA[rr][s].x + aA[rr][s].y)
                                     + (aB[rr][s].x + aB[rr][s].y);
                            t2 += __shfl_down_sync(0xffffffffu, t2, 1, 2);
                            v[rr][s] = t2;
                        }

                    int nxt = cur ^ 1;
                    if (kh == 0) {
#pragma unroll
                        for (int s = 0; s < 4; s++) {
                            float2 o;
                            o.x = fmaxf(xv[s].x + bj.x + v[0][s], 0.f);
                            o.y = fmaxf(xv[s].y + bj.y + v[1][s], 0.f);
                            *(float2*)(sm_h + nxt * BUF_STRIDE + s * SAMP_STRIDE + wslot) = o;
                            *(float2*)ho[s] = o;
                        }
                    }
#pragma unroll
                    for (int s = 0; s < 4; s++) ho[s] += HH;
                    __syncthreads();   // h(t) ready for step t+1
                    cur = nxt;
                }

                __threadfence();       // each thread fences its own h STGs
                __syncthreads();
                if (tid == 0)
                    ((volatile int*)g_hprog)[l * NQUAD + c] = (ch + 1) * CHUNK;
            }
        } else if (l < LL - 1) {
            // ===================== PROJ(l, c): h^l -> xp^{l+1} =====================
            float (*Ash)[17]  = (float(*)[17])smem_raw;
            float (*Bsh)[132] = (float(*)[132])(smem_raw + 8704);

            const float* Bw   = Wih + (size_t)l * HH * HH;
            const float* bias = bih + (size_t)l * HH;

            const int tx = tid & 15;      // 8 cols each
            const int ty = tid >> 4;      // 8 rows each

            for (int ch = 0; ch < NCHUNK; ch++) {
                if (tid == 0) {
                    const int need = (ch + 1) * CHUNK;
                    while (((volatile int*)g_hprog)[l * NQUAD + c] < need)
                        __nanosleep(200);
                }
                __syncthreads();
                __threadfence();   // acquire: order h reads after flag

#pragma unroll 1
                for (int sub = 0; sub < 8; sub++) {
                    const int s  = sub >> 1;                      // sample 0..3
                    const int cb = (sub & 1) * 128;               // col tile
                    const size_t rowbase = (size_t)(4 * c + s) * TT + ch * CHUNK;

                    float2 acc[8][4];
#pragma unroll
                    for (int i = 0; i < 8; i++)
#pragma unroll
                        for (int jp = 0; jp < 4; jp++) acc[i][jp] = make_float2(0.f, 0.f);

                    for (int kt = 0; kt < HH; kt += 16) {
#pragma unroll
                        for (int p = 0; p < 8; p++) {
                            int f = tid + p * 256;
                            int m = f >> 4, k = f & 15;
                            Ash[m][k] = (m < CHUNK)
                                ? g_h[(rowbase + m) * HH + kt + k] : 0.0f;
                        }
#pragma unroll
                        for (int p = 0; p < 8; p++) {
                            int f = tid + p * 256;
                            int n = f >> 4, k = f & 15;
                            Bsh[k][n] = Bw[(size_t)(cb + n) * HH + kt + k];
                        }
                        __syncthreads();
#pragma unroll
                        for (int kk = 0; kk < 16; kk++) {
                            float4 bv0 = *(const float4*)&Bsh[kk][tx * 8];
                            float4 bv1 = *(const float4*)&Bsh[kk][tx * 8 + 4];
                            float2 bp[4] = { {bv0.x, bv0.y}, {bv0.z, bv0.w},
                                             {bv1.x, bv1.y}, {bv1.z, bv1.w} };
#pragma unroll
                            for (int i = 0; i < 8; i++) {
                                float av = Ash[ty * 8 + i][kk];
                                float2 aa = {av, av};
#pragma unroll
                                for (int jp = 0; jp < 4; jp++)
                                    ffma2(acc[i][jp], aa, bp[jp]);
                            }
                        }
                        __syncthreads();
                    }

                    float bjv[8];
#pragma unroll
                    for (int jj = 0; jj < 8; jj++) bjv[jj] = bias[cb + tx * 8 + jj];
#pragma unroll
                    for (int i = 0; i < 8; i++) {
                        int m = ty * 8 + i;
                        if (m < CHUNK) {
#pragma unroll
                            for (int jp = 0; jp < 4; jp++) {
                                g_xp[(rowbase + m) * HH + cb + tx * 8 + 2 * jp]     = acc[i][jp].x + bjv[2 * jp];
                                g_xp[(rowbase + m) * HH + cb + tx * 8 + 2 * jp + 1] = acc[i][jp].y + bjv[2 * jp + 1];
                            }
                        }
                    }
                }

                // publish xp progress for layer l+1 (also releases the g_h
                // WAR hazard for scan(l+1,c))
                __threadfence();
                __syncthreads();
                if (tid == 0)
                    ((volatile int*)g_xprog)[(l + 1) * NQUAD + c] = (ch + 1) * CHUNK;
            }
        }
        __syncthreads();   // smem reuse barrier between tasks
    }
}

// ---------------------------------------------------------------------------
// Final FC: out[b,c] = sum_k h[b,T-1,k]*W_fc[c,k] + b_fc[c]
// ---------------------------------------------------------------------------
__global__ void fc_kernel(const float* __restrict__ Wfc,
                          const float* __restrict__ bfc,
                          float* __restrict__ out) {
    int b   = blockIdx.x;
    int tid = threadIdx.x;
    __shared__ float red[8];
    float hv = g_h[((size_t)b * TT + (TT - 1)) * HH + tid];
#pragma unroll
    for (int c = 0; c < CC; c++) {
        float p = hv * Wfc[(size_t)c * HH + tid];
#pragma unroll
        for (int o = 16; o > 0; o >>= 1)
            p += __shfl_down_sync(0xffffffffu, p, o);
        if ((tid & 31) == 0) red[tid >> 5] = p;
        __syncthreads();
        if (tid == 0) {
            float s = 0.0f;
#pragma unroll
            for (int w = 0; w < 8; w++) s += red[w];
            out[b * CC + c] = s + bfc[c];
        }
        __syncthreads();
    }
}

// ---------------------------------------------------------------------------
extern "C" void kernel_launch(void* const* d_in, const int* in_sizes, int n_in,
                              void* d_out, int out_size) {
    const float* x      = (const float*)d_in[0];
    const float* W_ih0  = (const float*)d_in[1];
    const float* b_ih0  = (const float*)d_in[2];
    const float* W_ih   = (const float*)d_in[3];
    const float* b_ih   = (const float*)d_in[4];
    const float* W_hh   = (const float*)d_in[5];
    const float* b_hh   = (const float*)d_in[6];
    const float* W_fc   = (const float*)d_in[7];
    const float* b_fc   = (const float*)d_in[8];
    float*       out    = (float*)d_out;

    static int smem_set = 0;
    if (!smem_set) {
        cudaFuncSetAttribute(wave_kernel,
                             cudaFuncAttributeMaxDynamicSharedMemorySize, SMEM_DYN);
        smem_set = 1;
    }

    proj0_kernel<<<BB * TT, HH>>>(x, W_ih0, b_ih0);
    wave_kernel<<<NCTA, 256, SMEM_DYN>>>(W_hh, b_hh, W_ih, b_ih);
    fc_kernel<<<BB, HH>>>(W_fc, b_fc, out);
}

// round 17
// speedup vs baseline: 1.4574x; 1.0346x over previous
#include <cuda_runtime.h>
#include <cstdint>

#define BB 128
#define TT 784
#define HH 256
#define LL 20
#define CC 10

#define NQUAD  32                     // 4 samples per scan task
#define CHUNK  112
#define NCHUNK 7                      // 7*112 = 784
#define NTASK  (LL * 2 * NQUAD)       // 1280
#define NCTA   152                    // GB300: 152 SMs (was 147 — 5 idle)

// Scratch (device globals: allocation-free per harness rules)
__device__ float g_xp[(size_t)BB * TT * HH];
__device__ float g_h [(size_t)BB * TT * HH];
__device__ int   g_hprog[LL * NQUAD];          // scan progress (t steps done)
__device__ int   g_xprog[LL * NQUAD];          // xp rows available for layer l
__device__ int   g_task;                        // dynamic task counter

// scan smem: h buffers [2 buf][4 samples][260 fl] = 8320B, then per-thread W
// (32 f4 data + 1 f4 pad = 132 fl stride -> 4-wf private reads, the floor).
// proj smem: Ash 128x17 @0, Bsh 16x132 @8704 (overlaid; tasks serialized).
#define SAMP_STRIDE 260               // 256 + 4 pad between kh halves
#define BUF_STRIDE  (4 * SAMP_STRIDE) // 1040
#define SM_W_OFF    8320
#define SM_W_STRIDE 132
#define SMEM_DYN    (SM_W_OFF + 256 * SM_W_STRIDE * 4)   // 143488

// ---------------------------------------------------------------------------
__device__ __forceinline__ void ffma2(float2& c, float2 a, float2 b) {
    union U { float2 f; unsigned long long u; };
    U A, Bv, C;
    A.f = a; Bv.f = b; C.f = c;
    asm("fma.rn.f32x2 %0, %1, %2, %3;"
        : "=l"(C.u) : "l"(A.u), "l"(Bv.u), "l"(C.u));
    c = C.f;
}

// ---------------------------------------------------------------------------
// Layer-0 projection + watermark/counter reset: xp = x*W0 + b0 (I==1)
// ---------------------------------------------------------------------------
__global__ void proj0_kernel(const float* __restrict__ x,
                             const float* __restrict__ W0,
                             const float* __restrict__ b0) {
    int row = blockIdx.x;
    int j   = threadIdx.x;
    if (j == 0 && row < LL * NQUAD) {           // replay-safe reset
        g_hprog[row] = 0;
        g_xprog[row] = (row < NQUAD) ? TT : 0;  // layer-0 xp filled here
        if (row == 0) g_task = 0;
    }
    g_xp[(size_t)row * HH + j] = x[row] * W0[j] + b0[j];
}

// ---------------------------------------------------------------------------
// Persistent wavefront kernel. 152 CTAs x 256 threads, dynamic task grab.
// Task q: l = q>>6, r = q&63, c = r>>1 (quad id), r&1 -> proj.
// Deps point to strictly smaller q; counter grab is monotone -> no deadlock
// (only resident CTAs grab; every grabbed task's deps were grabbed earlier
// by resident CTAs and complete).
// ---------------------------------------------------------------------------
__global__ __launch_bounds__(256, 1)
void wave_kernel(const float* __restrict__ Whh,
                 const float* __restrict__ bhh,
                 const float* __restrict__ Wih,
                 const float* __restrict__ bih) {
    extern __shared__ __align__(16) char smem_raw[];
    __shared__ int s_q;
    const int tid = threadIdx.x;

    for (;;) {
        if (tid == 0) s_q = atomicAdd(&g_task, 1);
        __syncthreads();
        const int q = s_q;
        __syncthreads();               // everyone read s_q before next overwrite
        if (q >= NTASK) break;

        const int l = q >> 6;
        const int r = q & 63;
        const int c = r >> 1;          // quad id 0..31

        if ((r & 1) == 0) {
            // ===================== SCAN(l, c): samples 4c..4c+3 =====================
            // Thread (j2 = tid>>1, kh = tid&1): cols c0 = 2*j2, c0+1;
            // k in [kh*128, +128). W row c0 in regs (32 f4), row c0+1 in
            // private smem (32 f4). FMA 2048 == crossbar 2048 per step/SM
            // (the fp32 dual-issue floor; 512 cyc per sample-step).
            float* sm_h = (float*)smem_raw;
            float* myw  = (float*)(smem_raw + SM_W_OFF) + tid * SM_W_STRIDE;

            const int j2 = tid >> 1;
            const int kh = tid & 1;
            const int c0 = 2 * j2;
            const int k0 = kh * 128;

            // Layer 19's h is only read at t=TT-1 (by FC); skip dead stores.
            const bool storeh = (l < LL - 1);

            const float* W0r = Whh + ((size_t)l * HH + c0) * HH + k0;
            const float* W1r = W0r + HH;

            float4 wr[32];
#pragma unroll
            for (int i = 0; i < 32; i++) wr[i] = *(const float4*)(W0r + 4 * i);
#pragma unroll
            for (int i = 0; i < 32; i++)
                *(float4*)(myw + 4 * i) = *(const float4*)(W1r + 4 * i);

            float2 bj = make_float2(0.f, 0.f);
            if (kh == 0) bj = *(const float2*)(bhh + l * HH + c0);

            for (int i = tid; i < 2 * BUF_STRIDE; i += 256) sm_h[i] = 0.0f;
            __syncthreads();

            const float* xp[4];
            float*       ho[4];
#pragma unroll
            for (int s = 0; s < 4; s++) {
                xp[s] = g_xp + (size_t)(4 * c + s) * TT * HH + c0;
                ho[s] = g_h  + (size_t)(4 * c + s) * TT * HH + c0;
            }

            const int rdo   = kh * 132;                 // read base within sample
            const int wslot = c0 + (c0 >= 128 ? 4 : 0); // write offset

            int cur = 0;
            for (int ch = 0; ch < NCHUNK; ch++) {
                if (tid == 0) {
                    const int need = (ch + 1) * CHUNK;
                    while (((volatile int*)g_xprog)[l * NQUAD + c] < need)
                        __nanosleep(200);
                }
                __syncthreads();
                __threadfence();   // acquire: order xp reads after flag

#pragma unroll 1
                for (int tt = 0; tt < CHUNK; tt++) {
                    float2 xv[4];
                    if (kh == 0) {
#pragma unroll
                        for (int s = 0; s < 4; s++) xv[s] = *(const float2*)xp[s];
                    }
#pragma unroll
                    for (int s = 0; s < 4; s++) xp[s] += HH;

                    const float* hb = sm_h + cur * BUF_STRIDE + rdo;

                    float2 aA[2][4], aB[2][4];   // [row][sample]
#pragma unroll
                    for (int rr = 0; rr < 2; rr++)
#pragma unroll
                        for (int s = 0; s < 4; s++) {
                            aA[rr][s] = make_float2(0.f, 0.f);
                            aB[rr][s] = make_float2(0.f, 0.f);
                        }

#pragma unroll
                    for (int i = 0; i < 32; i++) {
                        float4 w0 = wr[i];
                        float4 w1 = *(const float4*)(myw + 4 * i);
#pragma unroll
                        for (int s = 0; s < 4; s++) {
                            float4 h = *(const float4*)(hb + s * SAMP_STRIDE + 4 * i);
                            ffma2(aA[0][s], make_float2(w0.x, w0.y), make_float2(h.x, h.y));
                            ffma2(aB[0][s], make_float2(w0.z, w0.w), make_float2(h.z, h.w));
                            ffma2(aA[1][s], make_float2(w1.x, w1.y), make_float2(h.x, h.y));
                            ffma2(aB[1][s], make_float2(w1.z, w1.w), make_float2(h.z, h.w));
                        }
                    }

                    float v[2][4];
#pragma unroll
                    for (int rr = 0; rr < 2; rr++)
#pragma unroll
                        for (int s = 0; s < 4; s++) {
                            float t2 = (aA[rr][s].x + aA[rr][s].y)
                                     + (aB[rr][s].x + aB[rr][s].y);
                            t2 += __shfl_down_sync(0xffffffffu, t2, 1, 2);
                            v[rr][s] = t2;
                        }

                    int nxt = cur ^ 1;
                    if (kh == 0) {
                        const bool st = storeh ||
                                        (ch == NCHUNK - 1 && tt == CHUNK - 1);
#pragma unroll
                        for (int s = 0; s < 4; s++) {
                            float2 o;
                            o.x = fmaxf(xv[s].x + bj.x + v[0][s], 0.f);
                            o.y = fmaxf(xv[s].y + bj.y + v[1][s], 0.f);
                            *(float2*)(sm_h + nxt * BUF_STRIDE + s * SAMP_STRIDE + wslot) = o;
                            if (st) *(float2*)ho[s] = o;
                        }
                    }
#pragma unroll
                    for (int s = 0; s < 4; s++) ho[s] += HH;
                    __syncthreads();   // h(t) ready for step t+1
                    cur = nxt;
                }

                __threadfence();       // each thread fences its own h STGs
                __syncthreads();
                if (tid == 0)
                    ((volatile int*)g_hprog)[l * NQUAD + c] = (ch + 1) * CHUNK;
            }
        } else if (l < LL - 1) {
            // ===================== PROJ(l, c): h^l -> xp^{l+1} =====================
            float (*Ash)[17]  = (float(*)[17])smem_raw;
            float (*Bsh)[132] = (float(*)[132])(smem_raw + 8704);

            const float* Bw   = Wih + (size_t)l * HH * HH;
            const float* bias = bih + (size_t)l * HH;

            const int tx = tid & 15;      // 8 cols each
            const int ty = tid >> 4;      // 8 rows each

            for (int ch = 0; ch < NCHUNK; ch++) {
                if (tid == 0) {
                    const int need = (ch + 1) * CHUNK;
                    while (((volatile int*)g_hprog)[l * NQUAD + c] < need)
                        __nanosleep(200);
                }
                __syncthreads();
                __threadfence();   // acquire: order h reads after flag

#pragma unroll 1
                for (int sub = 0; sub < 8; sub++) {
                    const int s  = sub >> 1;                      // sample 0..3
                    const int cb = (sub & 1) * 128;               // col tile
                    const size_t rowbase = (size_t)(4 * c + s) * TT + ch * CHUNK;

                    float2 acc[8][4];
#pragma unroll
                    for (int i = 0; i < 8; i++)
#pragma unroll
                        for (int jp = 0; jp < 4; jp++) acc[i][jp] = make_float2(0.f, 0.f);

                    for (int kt = 0; kt < HH; kt += 16) {
#pragma unroll
                        for (int p = 0; p < 8; p++) {
                            int f = tid + p * 256;
                            int m = f >> 4, k = f & 15;
                            Ash[m][k] = (m < CHUNK)
                                ? g_h[(rowbase + m) * HH + kt + k] : 0.0f;
                        }
#pragma unroll
                        for (int p = 0; p < 8; p++) {
                            int f = tid + p * 256;
                            int n = f >> 4, k = f & 15;
                            Bsh[k][n] = Bw[(size_t)(cb + n) * HH + kt + k];
                        }
                        __syncthreads();
#pragma unroll
                        for (int kk = 0; kk < 16; kk++) {
                            float4 bv0 = *(const float4*)&Bsh[kk][tx * 8];
                            float4 bv1 = *(const float4*)&Bsh[kk][tx * 8 + 4];
                            float2 bp[4] = { {bv0.x, bv0.y}, {bv0.z, bv0.w},
                                             {bv1.x, bv1.y}, {bv1.z, bv1.w} };
#pragma unroll
                            for (int i = 0; i < 8; i++) {
                                float av = Ash[ty * 8 + i][kk];
                                float2 aa = {av, av};
#pragma unroll
                                for (int jp = 0; jp < 4; jp++)
                                    ffma2(acc[i][jp], aa, bp[jp]);
                            }
                        }
                        __syncthreads();
                    }

                    float bjv[8];
#pragma unroll
                    for (int jj = 0; jj < 8; jj++) bjv[jj] = bias[cb + tx * 8 + jj];
#pragma unroll
                    for (int i = 0; i < 8; i++) {
                        int m = ty * 8 + i;
                        if (m < CHUNK) {
#pragma unroll
                            for (int jp = 0; jp < 4; jp++) {
                                g_xp[(rowbase + m) * HH + cb + tx * 8 + 2 * jp]     = acc[i][jp].x + bjv[2 * jp];
                                g_xp[(rowbase + m) * HH + cb + tx * 8 + 2 * jp + 1] = acc[i][jp].y + bjv[2 * jp + 1];
                            }
                        }
                    }
                }

                // publish xp progress for layer l+1 (also releases the g_h
                // WAR hazard for scan(l+1,c))
                __threadfence();
                __syncthreads();
                if (tid == 0)
                    ((volatile int*)g_xprog)[(l + 1) * NQUAD + c] = (ch + 1) * CHUNK;
            }
        }
        __syncthreads();   // smem reuse barrier between tasks
    }
}

// ---------------------------------------------------------------------------
// Final FC: out[b,c] = sum_k h[b,T-1,k]*W_fc[c,k] + b_fc[c]
// ---------------------------------------------------------------------------
__global__ void fc_kernel(const float* __restrict__ Wfc,
                          const float* __restrict__ bfc,
                          float* __restrict__ out) {
    int b   = blockIdx.x;
    int tid = threadIdx.x;
    __shared__ float red[8];
    float hv = g_h[((size_t)b * TT + (TT - 1)) * HH + tid];
#pragma unroll
    for (int c = 0; c < CC; c++) {
        float p = hv * Wfc[(size_t)c * HH + tid];
#pragma unroll
        for (int o = 16; o > 0; o >>= 1)
            p += __shfl_down_sync(0xffffffffu, p, o);
        if ((tid & 31) == 0) red[tid >> 5] = p;
        __syncthreads();
        if (tid == 0) {
            float s = 0.0f;
#pragma unroll
            for (int w = 0; w < 8; w++) s += red[w];
            out[b * CC + c] = s + bfc[c];
        }
        __syncthreads();
    }
}

// ---------------------------------------------------------------------------
extern "C" void kernel_launch(void* const* d_in, const int* in_sizes, int n_in,
                              void* d_out, int out_size) {
    const float* x      = (const float*)d_in[0];
    const float* W_ih0  = (const float*)d_in[1];
    const float* b_ih0  = (const float*)d_in[2];
    const float* W_ih   = (const float*)d_in[3];
    const float* b_ih   = (const float*)d_in[4];
    const float* W_hh   = (const float*)d_in[5];
    const float* b_hh   = (const float*)d_in[6];
    const float* W_fc   = (const float*)d_in[7];
    const float* b_fc   = (const float*)d_in[8];
    float*       out    = (float*)d_out;

    static int smem_set = 0;
    if (!smem_set) {
        cudaFuncSetAttribute(wave_kernel,
                             cudaFuncAttributeMaxDynamicSharedMemorySize, SMEM_DYN);
        smem_set = 1;
    }

    proj0_kernel<<<BB * TT, HH>>>(x, W_ih0, b_ih0);
    wave_kernel<<<NCTA, 256, SMEM_DYN>>>(W_hh, b_hh, W_ih, b_ih);
    fc_kernel<<<BB, HH>>>(W_fc, b_fc, out);
}